// round 5
// baseline (speedup 1.0000x reference)
#include <cuda_runtime.h>

// Sinkhorn: s[64,1024,1024] fp32, 10 alternating masked normalizations.
// Rank-one factorization: s_final = (s0+eps) * r_i * c_j inside the
// [nrows[b], ncols[b]] block, 0 outside. Each iteration REPLACES one of
// r/c via a masked matvec over the original matrix.

#define BB 64
#define NN 1024
#define MM 1024
#define SPLIT 8
#define EPSV 1e-4f

// Scratch (device globals: no allocation allowed in kernel_launch)
__device__ float g_r[BB * NN];                 // 256 KB
__device__ float g_c[BB * MM];                 // 256 KB
__device__ float g_part[BB * SPLIT * MM];      // 2 MB

// ---------------------------------------------------------------------------
// Column sums: part[b, split, j] = sum over row-chunk of (s+eps)*r_i, j<ncols.
// Thread = one column j; loads are coalesced 128B per warp per row step.
// USE_R=false for iteration 0 (implicit r=1) -> no init kernel needed.
// ---------------------------------------------------------------------------
template <bool USE_R>
__global__ void colsum_kernel(const float* __restrict__ s,
                              const int* __restrict__ nrows,
                              const int* __restrict__ ncols) {
    int b = blockIdx.z;
    int j = blockIdx.x * blockDim.x + threadIdx.x;
    int nr = nrows[b];
    int nc = ncols[b];
    int chunk = (nr + SPLIT - 1) / SPLIT;
    int i0 = blockIdx.y * chunk;
    int i1 = min(i0 + chunk, nr);

    float acc0 = 0.f, acc1 = 0.f;
    if (j < nc && i0 < i1) {
        const float* p = s + ((size_t)b * NN + i0) * MM + j;
        const float* rp = g_r + b * NN + i0;
        int n = i1 - i0;
        int i = 0;
        #pragma unroll 4
        for (; i + 2 <= n; i += 2) {
            float a0 = p[(size_t)i * MM] + EPSV;
            float a1 = p[(size_t)(i + 1) * MM] + EPSV;
            if (USE_R) {
                acc0 += a0 * rp[i];
                acc1 += a1 * rp[i + 1];
            } else {
                acc0 += a0;
                acc1 += a1;
            }
        }
        if (i < n) {
            float a0 = p[(size_t)i * MM] + EPSV;
            acc0 += USE_R ? a0 * rp[i] : a0;
        }
    }
    g_part[((size_t)b * SPLIT + blockIdx.y) * MM + j] = acc0 + acc1;
}

// ---------------------------------------------------------------------------
// c[b,j] = 1 / sum_k part[b,k,j]   (j < ncols; else 1.0 to avoid inf)
// ---------------------------------------------------------------------------
__global__ void reduce_c_kernel(const int* __restrict__ ncols) {
    int b = blockIdx.y;
    int j = blockIdx.x * blockDim.x + threadIdx.x;
    float sum = 0.f;
    #pragma unroll
    for (int k = 0; k < SPLIT; k++)
        sum += g_part[((size_t)b * SPLIT + k) * MM + j];
    int nc = ncols[b];
    g_c[b * MM + j] = (j < nc) ? (1.0f / sum) : 1.0f;
}

// ---------------------------------------------------------------------------
// r[b,i] = 1 / sum_{j<ncols} (s+eps)*c_j.  One warp per valid row.
// Rows i >= nrows are skipped (their r is never read anywhere).
// ---------------------------------------------------------------------------
__global__ void rowsum_kernel(const float* __restrict__ s,
                              const int* __restrict__ nrows,
                              const int* __restrict__ ncols) {
    int b = blockIdx.y;
    int lane = threadIdx.x & 31;
    int w = threadIdx.x >> 5;
    int i = blockIdx.x * (blockDim.x >> 5) + w;
    int nr = nrows[b];
    if (i >= nr) return;
    int nc = ncols[b];

    const float* p = s + ((size_t)b * NN + i) * MM;
    const float* cp = g_c + b * MM;
    float acc = 0.f;
    #pragma unroll 4
    for (int j = lane; j < nc; j += 32)
        acc += (p[j] + EPSV) * cp[j];

    #pragma unroll
    for (int off = 16; off; off >>= 1)
        acc += __shfl_down_sync(0xffffffffu, acc, off);

    if (lane == 0) g_r[b * NN + i] = 1.0f / acc;
}

// ---------------------------------------------------------------------------
// out[b,i,j] = block ? (s+eps)*r_i*c_j : 0.   float4 vectorized.
// d_out is poisoned, so zeros outside the block MUST be written.
// ---------------------------------------------------------------------------
__global__ void final_kernel(const float* __restrict__ s,
                             const int* __restrict__ nrows,
                             const int* __restrict__ ncols,
                             float* __restrict__ out) {
    size_t idx = (size_t)blockIdx.x * blockDim.x + threadIdx.x;  // one float4
    size_t row = idx >> 8;            // MM/4 = 256 float4 per row
    int b = (int)(row >> 10);         // NN = 1024 rows per batch
    int i = (int)(row & (NN - 1));
    int j = (int)((idx & 255) << 2);
    int nr = nrows[b];
    int nc = ncols[b];

    float4 v = ((const float4*)s)[idx];
    float4 c = ((const float4*)g_c)[((size_t)b * MM + j) >> 2];
    float r = g_r[row];               // only meaningful when i < nr
    bool rok = (i < nr);

    float4 o;
    o.x = (rok && (j + 0) < nc) ? (v.x + EPSV) * r * c.x : 0.f;
    o.y = (rok && (j + 1) < nc) ? (v.y + EPSV) * r * c.y : 0.f;
    o.z = (rok && (j + 2) < nc) ? (v.z + EPSV) * r * c.z : 0.f;
    o.w = (rok && (j + 3) < nc) ? (v.w + EPSV) * r * c.w : 0.f;
    ((float4*)out)[idx] = o;
}

// ---------------------------------------------------------------------------
extern "C" void kernel_launch(void* const* d_in, const int* in_sizes, int n_in,
                              void* d_out, int out_size) {
    const float* s     = (const float*)d_in[0];
    const int*   nrows = (const int*)d_in[1];
    const int*   ncols = (const int*)d_in[2];
    float*       out   = (float*)d_out;

    dim3 csGrid(MM / 256, SPLIT, BB), csBlk(256);
    dim3 rcGrid(MM / 256, BB),        rcBlk(256);
    dim3 rsGrid(NN / 8, BB),          rsBlk(256);   // 8 warps/block, warp per row

    // iter 0 (even, col-norm) with implicit r = 1
    colsum_kernel<false><<<csGrid, csBlk>>>(s, nrows, ncols);
    reduce_c_kernel<<<rcGrid, rcBlk>>>(ncols);
    // iter 1 (odd, row-norm)
    rowsum_kernel<<<rsGrid, rsBlk>>>(s, nrows, ncols);

    // iters 2..9: 4 more (col, row) pairs
    for (int p = 0; p < 4; ++p) {
        colsum_kernel<true><<<csGrid, csBlk>>>(s, nrows, ncols);
        reduce_c_kernel<<<rcGrid, rcBlk>>>(ncols);
        rowsum_kernel<<<rsGrid, rsBlk>>>(s, nrows, ncols);
    }

    // materialize output
    size_t total4 = (size_t)BB * NN * MM / 4;          // 16M float4
    final_kernel<<<(unsigned)(total4 / 256), 256>>>(s, nrows, ncols, out);
}

// round 7
// speedup vs baseline: 1.6796x; 1.6796x over previous
#include <cuda_runtime.h>
#include <cuda_fp16.h>

// Sinkhorn rank-one factorization: out = (s0+eps)*r_i*c_j inside the
// [nrows, ncols] block. 10 alternating matvecs; matvecs run on an fp16
// staged copy of (s0+eps) (zero-padded past ncols), output from fp32 s0.

#define BB 64
#define NN 1024
#define MM 1024
#define SPLIT 16
#define EPSV 1e-4f

// Device-global scratch (no runtime allocation allowed)
__device__ __align__(16) __half g_sh[(size_t)BB * NN * MM];   // 128 MB (bss)
__device__ __align__(16) float  g_r[BB * NN];
__device__ __align__(16) float  g_c[BB * MM];
__device__ __align__(16) float  g_part[(size_t)BB * SPLIT * MM];

// ---------------------------------------------------------------------------
// Fused: convert valid rows of (s+eps) -> fp16 (zero past ncols) AND compute
// iteration-0 column-sum partials (implicit r = 1).
// Thread t owns 4 consecutive columns; block handles a row chunk.
// ---------------------------------------------------------------------------
__global__ __launch_bounds__(256) void stage_colsum0(
        const float* __restrict__ s,
        const int* __restrict__ nrows,
        const int* __restrict__ ncols) {
    int b = blockIdx.y;
    int t = threadIdx.x;                    // 256 threads * 4 cols = 1024
    int nr = nrows[b], nc = ncols[b];
    int chunk = (nr + SPLIT - 1) / SPLIT;
    int i0 = blockIdx.x * chunk;
    int i1 = min(i0 + chunk, nr);
    int j = t * 4;
    bool m0 = j < nc, m1 = j + 1 < nc, m2 = j + 2 < nc, m3 = j + 3 < nc;

    float4 acc = make_float4(0.f, 0.f, 0.f, 0.f);
    const float4* __restrict__ sp =
        (const float4*)(s + ((size_t)b * NN + i0) * MM) + t;
    __half2* __restrict__ hp =
        (__half2*)(g_sh + ((size_t)b * NN + i0) * MM) + t * 2;

    for (int i = i0; i < i1; i++) {
        float x0 = 0.f, x1 = 0.f, x2 = 0.f, x3 = 0.f;
        if (m0) {
            float4 v = *sp;
            x0 = v.x + EPSV;
            x1 = m1 ? v.y + EPSV : 0.f;
            x2 = m2 ? v.z + EPSV : 0.f;
            x3 = m3 ? v.w + EPSV : 0.f;
        }
        hp[0] = __floats2half2_rn(x0, x1);
        hp[1] = __floats2half2_rn(x2, x3);
        acc.x += x0; acc.y += x1; acc.z += x2; acc.w += x3;
        sp += MM / 4;
        hp += MM / 2;
    }
    ((float4*)(g_part + ((size_t)b * SPLIT + blockIdx.x) * MM))[t] = acc;
}

// ---------------------------------------------------------------------------
// c[b,j] = 1 / sum_k part[b,k,j]  (j < ncols; else 1.0)
// ---------------------------------------------------------------------------
__global__ __launch_bounds__(256) void reduce_c_kernel(
        const int* __restrict__ ncols) {
    int b = blockIdx.y;
    int j = blockIdx.x * 256 + threadIdx.x;
    float sum = 0.f;
    #pragma unroll
    for (int k = 0; k < SPLIT; k++)
        sum += g_part[((size_t)b * SPLIT + k) * MM + j];
    g_c[b * MM + j] = (j < ncols[b]) ? (1.0f / sum) : 1.0f;
}

// ---------------------------------------------------------------------------
// Column-sum partials on staged fp16, weighted by r: thread owns 4 cols.
// Staged is zero-padded past ncols, rows limited to nrows -> no inner masks.
// ---------------------------------------------------------------------------
__global__ __launch_bounds__(256) void colsum_h(
        const int* __restrict__ nrows,
        const int* __restrict__ ncols) {
    int b = blockIdx.y;
    int t = threadIdx.x;
    int nr = nrows[b], nc = ncols[b];
    int chunk = (nr + SPLIT - 1) / SPLIT;
    int i0 = blockIdx.x * chunk;
    int i1 = min(i0 + chunk, nr);

    float4 acc = make_float4(0.f, 0.f, 0.f, 0.f);
    if (t * 4 < nc) {
        const float2* __restrict__ hp =
            (const float2*)(g_sh + ((size_t)b * NN + i0) * MM) + t;
        const float* __restrict__ rp = g_r + b * NN;
        #pragma unroll 4
        for (int i = i0; i < i1; i++) {
            float2 raw = hp[(size_t)(i - i0) * (MM / 4)];
            __half2 h0 = *(__half2*)&raw.x;
            __half2 h1 = *(__half2*)&raw.y;
            float2 a = __half22float2(h0);
            float2 d = __half22float2(h1);
            float r = rp[i];
            acc.x += a.x * r; acc.y += a.y * r;
            acc.z += d.x * r; acc.w += d.y * r;
        }
    }
    ((float4*)(g_part + ((size_t)b * SPLIT + blockIdx.x) * MM))[t] = acc;
}

// ---------------------------------------------------------------------------
// r[b,i] = 1 / sum_j staged[b,i,j] * c[b,j].  Warp per valid row.
// Zero padding makes the last partial group safe (0 * 1.0).
// ---------------------------------------------------------------------------
__global__ __launch_bounds__(256) void rowsum_h(
        const int* __restrict__ nrows,
        const int* __restrict__ ncols) {
    int b = blockIdx.y;
    int lane = threadIdx.x & 31, w = threadIdx.x >> 5;
    int i = blockIdx.x * 8 + w;
    if (i >= nrows[b]) return;
    int nc = ncols[b];

    const float2* __restrict__ hp =
        (const float2*)(g_sh + ((size_t)b * NN + i) * MM);
    const float4* __restrict__ cp = (const float4*)(g_c + (size_t)b * MM);
    float acc = 0.f;
    int ng = (nc + 3) >> 2;
    #pragma unroll 4
    for (int j4 = lane; j4 < ng; j4 += 32) {
        float2 raw = hp[j4];
        __half2 h0 = *(__half2*)&raw.x;
        __half2 h1 = *(__half2*)&raw.y;
        float2 a = __half22float2(h0);
        float2 d = __half22float2(h1);
        float4 c = cp[j4];
        acc += a.x * c.x + a.y * c.y + d.x * c.z + d.y * c.w;
    }
    #pragma unroll
    for (int o = 16; o; o >>= 1) acc += __shfl_xor_sync(0xffffffffu, acc, o);
    if (lane == 0) g_r[b * NN + i] = 1.0f / acc;
}

// ---------------------------------------------------------------------------
// Fused iteration-9 rowsum + output: warp computes r for its row from staged
// fp16, then writes out = (s+eps)*r*c (fp32 read only inside valid cols).
// Invalid rows write zeros without touching s.
// ---------------------------------------------------------------------------
__global__ __launch_bounds__(256) void rowsum_final(
        const float* __restrict__ s,
        const int* __restrict__ nrows,
        const int* __restrict__ ncols,
        float* __restrict__ out) {
    int b = blockIdx.y;
    int lane = threadIdx.x & 31, w = threadIdx.x >> 5;
    int i = blockIdx.x * 8 + w;
    int nr = nrows[b], nc = ncols[b];
    float4* __restrict__ op = (float4*)(out + ((size_t)b * NN + i) * MM);

    if (i >= nr) {
        float4 z = make_float4(0.f, 0.f, 0.f, 0.f);
        #pragma unroll 2
        for (int k = lane; k < MM / 4; k += 32) op[k] = z;
        return;
    }

    const float2* __restrict__ hp =
        (const float2*)(g_sh + ((size_t)b * NN + i) * MM);
    const float4* __restrict__ cp = (const float4*)(g_c + (size_t)b * MM);
    float acc = 0.f;
    int ng = (nc + 3) >> 2;
    #pragma unroll 4
    for (int j4 = lane; j4 < ng; j4 += 32) {
        float2 raw = hp[j4];
        __half2 h0 = *(__half2*)&raw.x;
        __half2 h1 = *(__half2*)&raw.y;
        float2 a = __half22float2(h0);
        float2 d = __half22float2(h1);
        float4 c = cp[j4];
        acc += a.x * c.x + a.y * c.y + d.x * c.z + d.y * c.w;
    }
    #pragma unroll
    for (int o = 16; o; o >>= 1) acc += __shfl_xor_sync(0xffffffffu, acc, o);
    float r = 1.0f / acc;

    const float4* __restrict__ sp =
        (const float4*)(s + ((size_t)b * NN + i) * MM);
    #pragma unroll 2
    for (int k = lane; k < MM / 4; k += 32) {
        int j = k * 4;
        float4 o4 = make_float4(0.f, 0.f, 0.f, 0.f);
        if (j < nc) {
            float4 v = sp[k];
            float4 c = cp[k];
            o4.x = (v.x + EPSV) * r * c.x;
            if (j + 1 < nc) o4.y = (v.y + EPSV) * r * c.y;
            if (j + 2 < nc) o4.z = (v.z + EPSV) * r * c.z;
            if (j + 3 < nc) o4.w = (v.w + EPSV) * r * c.w;
        }
        op[k] = o4;
    }
}

// ---------------------------------------------------------------------------
extern "C" void kernel_launch(void* const* d_in, const int* in_sizes, int n_in,
                              void* d_out, int out_size) {
    const float* s     = (const float*)d_in[0];
    const int*   nrows = (const int*)d_in[1];
    const int*   ncols = (const int*)d_in[2];
    float*       out   = (float*)d_out;

    dim3 csGrid(SPLIT, BB),    blk(256);
    dim3 rcGrid(MM / 256, BB);
    dim3 rsGrid(NN / 8, BB);

    // iter 0 (col): fused stage + colsum with implicit r = 1
    stage_colsum0<<<csGrid, blk>>>(s, nrows, ncols);
    reduce_c_kernel<<<rcGrid, blk>>>(ncols);
    // iter 1 (row)
    rowsum_h<<<rsGrid, blk>>>(nrows, ncols);

    // iters 2..7: three (col, row) pairs on staged fp16
    for (int p = 0; p < 3; ++p) {
        colsum_h<<<csGrid, blk>>>(nrows, ncols);
        reduce_c_kernel<<<rcGrid, blk>>>(ncols);
        rowsum_h<<<rsGrid, blk>>>(nrows, ncols);
    }
    // iter 8 (col)
    colsum_h<<<csGrid, blk>>>(nrows, ncols);
    reduce_c_kernel<<<rcGrid, blk>>>(ncols);
    // iter 9 (row) fused with output materialization
    rowsum_final<<<rsGrid, blk>>>(s, nrows, ncols, out);
}